// round 17
// baseline (speedup 1.0000x reference)
#include <cuda_runtime.h>

#define TT   2048
#define DD   64
#define HH   64
#define NG   256
#define WIN  8                 // steps per window
#define NWINS (TT / WIN)       // 256
#define RING 32                // xg ring slots (4 windows)

// Dynamic SMEM layout (floats):
//  XGR: [2][RING][NG]      xg ring per batch (scalar, R12 layout)
//  XST: [4][2][WIN][DD]    x stage ring (4 windows)
//  HS : [2 batch][2 buf][HH]  h double buffer
#define XGR_OFF 0
#define XST_OFF 16384
#define HS_OFF  (16384 + 4096)
#define SMEM_FLOATS (HS_OFF + 256)
#define SMEM_BYTES  (SMEM_FLOATS * 4)   // 82,944 B

__device__ __forceinline__ unsigned long long ffma2(unsigned long long a,
                                                    unsigned long long b,
                                                    unsigned long long c) {
    unsigned long long d;
    asm("fma.rn.f32x2 %0, %1, %2, %3;" : "=l"(d) : "l"(a), "l"(b), "l"(c));
    return d;
}
__device__ __forceinline__ float red2(unsigned long long v) {
    float lo, hi;
    asm("mov.b64 {%0, %1}, %2;" : "=f"(lo), "=f"(hi) : "l"(v));
    return lo + hi;
}
__device__ __forceinline__ float tanh_ap(float x) {
    float y;
    asm("tanh.approx.f32 %0, %1;" : "=f"(y) : "f"(x));
    return y;
}
__device__ __forceinline__ float sigm_ap(float x) {
    return fmaf(0.5f, tanh_ap(0.5f * x), 0.5f);
}

// ---------------------------------------------------------------------------
// grid=128, block=256.
//   tid   0..63  : rec, batch 2*bid   — thread u owns ALL 4 gates of unit u
//                  (no shfl in the cell update), bar.sync 1,64 per step.
//   tid  64..127 : rec, batch 2*bid+1 — same, bar.sync 2,64 per step.
//   tid 128..255 : producer (R12 verbatim) — xg = bias + W_ih.x for both
//                  batches, 3 windows ahead into the scalar ring; x staged
//                  GMEM->SMEM 4 windows ahead.
//   __syncthreads() once per 8-step window joins everything.
// ---------------------------------------------------------------------------
__global__ void __launch_bounds__(256, 1)
lstm_q4(const float* __restrict__ x, const float* __restrict__ w_ih,
        const float* __restrict__ w_hh, const float* __restrict__ b_ih,
        const float* __restrict__ b_hh, const float* __restrict__ fc_w,
        const float* __restrict__ fc_b, float* __restrict__ out)
{
    extern __shared__ __align__(16) float sm[];
    float* XGR = sm + XGR_OFF;   // [bb][slot][gate] scalar
    float* XST = sm + XST_OFF;   // [sslot][bb][t'][k]
    float* HS  = sm + HS_OFF;    // [bb][buf][u]

    const int tid = threadIdx.x;
    const int b0  = blockIdx.x * 2;
    const bool is_rec = (tid < 128);

    // ---------- prologue: cooperatively stage x windows 0..3 ----------
    {
#pragma unroll
        for (int r = 0; r < 4; ++r) {
            int idx = tid + r * 256;            // 0..1023 float4s
            int win = idx >> 8;
            int wi  = idx & 255;
            int bb  = wi >> 7;
            int rem = wi & 127;
            int tq  = rem >> 4;
            int q   = rem & 15;
            float4 v = ((const float4*)(x +
                        ((size_t)(b0 + bb) * TT + win * WIN + tq) * DD))[q];
            ((float4*)(XST + win * (2 * WIN * DD)))[wi] = v;
        }
    }
    __syncthreads();

    // ===================== REC side state =====================
    int grp = 0, lu = 0, barid = 1;
    ulonglong2 wi4[16], wf4[16], wg4[16], wo4[16];
    // ===================== PROD side state ====================
    int pt = tid - 128;
    int pga = pt, pgb = pt + 128;
    ulonglong2 wpa[16], wpb[16];
    float bpa = 0.f, bpb = 0.f;

    if (is_rec) {
        grp = tid >> 6;          // batch within block
        lu  = tid & 63;          // unit
        barid = grp + 1;
        const ulonglong2* pwi = (const ulonglong2*)(w_hh + (lu)       * HH);
        const ulonglong2* pwf = (const ulonglong2*)(w_hh + (lu + 64)  * HH);
        const ulonglong2* pwg = (const ulonglong2*)(w_hh + (lu + 128) * HH);
        const ulonglong2* pwo = (const ulonglong2*)(w_hh + (lu + 192) * HH);
#pragma unroll
        for (int j = 0; j < 16; ++j) {
            wi4[j] = pwi[j]; wf4[j] = pwf[j];
            wg4[j] = pwg[j]; wo4[j] = pwo[j];
        }
        if (tid < 128) { HS[tid] = 0.f; HS[tid + 128] = 0.f; }
    } else {
        const ulonglong2* pa = (const ulonglong2*)(w_ih + (size_t)pga * DD);
        const ulonglong2* pb = (const ulonglong2*)(w_ih + (size_t)pgb * DD);
#pragma unroll
        for (int j = 0; j < 16; ++j) { wpa[j] = pa[j]; wpb[j] = pb[j]; }
        bpa = b_ih[pga] + b_hh[pga];
        bpb = b_ih[pgb] + b_hh[pgb];

        // prologue: compute windows 0,1,2 into the xg ring (R12 verbatim)
        for (int wc = 0; wc < 3; ++wc) {
            const float* xw = XST + (wc & 3) * (2 * WIN * DD);
#pragma unroll
            for (int bb = 0; bb < 2; ++bb) {
                unsigned long long aa[8], ab[8];
#pragma unroll
                for (int i = 0; i < 8; ++i) { aa[i] = 0ull; ab[i] = 0ull; }
#pragma unroll
                for (int j = 0; j < 16; ++j) {
                    ulonglong2 wja = wpa[j], wjb = wpb[j];
#pragma unroll
                    for (int i = 0; i < 8; ++i) {
                        ulonglong2 xv = *(const ulonglong2*)(xw + bb * WIN * DD
                                                             + i * DD + j * 4);
                        aa[i] = ffma2(wja.x, xv.x, aa[i]);
                        aa[i] = ffma2(wja.y, xv.y, aa[i]);
                        ab[i] = ffma2(wjb.x, xv.x, ab[i]);
                        ab[i] = ffma2(wjb.y, xv.y, ab[i]);
                    }
                }
#pragma unroll
                for (int i = 0; i < 8; ++i) {
                    int slot = (wc * WIN + i) & (RING - 1);
                    XGR[bb * (RING * NG) + slot * NG + pga] = bpa + red2(aa[i]);
                    XGR[bb * (RING * NG) + slot * NG + pgb] = bpb + red2(ab[i]);
                }
            }
        }
    }
    __syncthreads();

    float c = 0.f;   // cell state for unit lu, batch grp (thread-local!)

    for (int w = 0; w < NWINS; ++w) {
        if (is_rec) {
            float* hb = HS + grp * 128;
            const float* xgg = XGR + grp * (RING * NG);
            // ---------------- 8 recurrence steps ----------------
#pragma unroll
            for (int i = 0; i < 8; ++i) {
                const int t = w * WIN + i;
                const int slot = t & (RING - 1);

                // load h once into registers; reuse across all 4 gate dots
                ulonglong2 hreg[16];
                const ulonglong2* hv = (const ulonglong2*)(hb + (t & 1) * 64);
#pragma unroll
                for (int j = 0; j < 16; ++j) hreg[j] = hv[j];

                unsigned long long I0 = 0ull, I1 = 0ull, F0 = 0ull, F1 = 0ull;
                unsigned long long G0 = 0ull, G1 = 0ull, O0 = 0ull, O1 = 0ull;
#pragma unroll
                for (int j = 0; j < 16; ++j) {
                    ulonglong2 h2 = hreg[j];
                    I0 = ffma2(wi4[j].x, h2.x, I0);
                    I1 = ffma2(wi4[j].y, h2.y, I1);
                    F0 = ffma2(wf4[j].x, h2.x, F0);
                    F1 = ffma2(wf4[j].y, h2.y, F1);
                    G0 = ffma2(wg4[j].x, h2.x, G0);
                    G1 = ffma2(wg4[j].y, h2.y, G1);
                    O0 = ffma2(wo4[j].x, h2.x, O0);
                    O1 = ffma2(wo4[j].y, h2.y, O1);
                }
                float si = xgg[slot * NG + lu]       + red2(I0) + red2(I1);
                float sf = xgg[slot * NG + lu + 64]  + red2(F0) + red2(F1);
                float sg = xgg[slot * NG + lu + 128] + red2(G0) + red2(G1);
                float so = xgg[slot * NG + lu + 192] + red2(O0) + red2(O1);

                float gi = sigm_ap(si);
                float gf = sigm_ap(sf);
                float gg = tanh_ap(sg);
                float go = sigm_ap(so);
                c = fmaf(gf, c, gi * gg);
                hb[((t + 1) & 1) * 64 + lu] = go * tanh_ap(c);

                asm volatile("bar.sync %0, 64;" :: "r"(barid));
            }
        } else {
            // ---------------- producer (R12 verbatim) ----------------
            const int wl = w + 4;          // window to stage
            const int wc = w + 3;          // window to compute
            float4 r0, r1;
            if (wl < NWINS) {
                int idx0 = pt, idx1 = pt + 128;
                int bb0 = idx0 >> 7, tq0 = (idx0 & 127) >> 4, q0 = idx0 & 15;
                int bb1 = idx1 >> 7, tq1 = (idx1 & 127) >> 4, q1 = idx1 & 15;
                r0 = ((const float4*)(x + ((size_t)(b0 + bb0) * TT
                                           + wl * WIN + tq0) * DD))[q0];
                r1 = ((const float4*)(x + ((size_t)(b0 + bb1) * TT
                                           + wl * WIN + tq1) * DD))[q1];
            }
            if (wc < NWINS) {
                const float* xw = XST + (wc & 3) * (2 * WIN * DD);
#pragma unroll
                for (int bb = 0; bb < 2; ++bb) {
                    unsigned long long aa[8], ab[8];
#pragma unroll
                    for (int i = 0; i < 8; ++i) { aa[i] = 0ull; ab[i] = 0ull; }
#pragma unroll
                    for (int j = 0; j < 16; ++j) {
                        ulonglong2 wja = wpa[j], wjb = wpb[j];
#pragma unroll
                        for (int i = 0; i < 8; ++i) {
                            ulonglong2 xv = *(const ulonglong2*)(xw
                                            + bb * WIN * DD + i * DD + j * 4);
                            aa[i] = ffma2(wja.x, xv.x, aa[i]);
                            aa[i] = ffma2(wja.y, xv.y, aa[i]);
                            ab[i] = ffma2(wjb.x, xv.x, ab[i]);
                            ab[i] = ffma2(wjb.y, xv.y, ab[i]);
                        }
                    }
#pragma unroll
                    for (int i = 0; i < 8; ++i) {
                        int slot = (wc * WIN + i) & (RING - 1);
                        XGR[bb * (RING * NG) + slot * NG + pga] = bpa + red2(aa[i]);
                        XGR[bb * (RING * NG) + slot * NG + pgb] = bpb + red2(ab[i]);
                    }
                }
            }
            if (wl < NWINS) {   // stage into slot wl&3 == w&3 (window w's x is dead)
                float4* dst = (float4*)(XST + (wl & 3) * (2 * WIN * DD));
                dst[pt]       = r0;
                dst[pt + 128] = r1;
            }
        }
        __syncthreads();
    }

    // ---- final FC: out[b, o] = h_last . fc_w[o] + fc_b[o] ----
    if (tid < 16) {
        int bb = tid >> 3, o = tid & 7;
        const float* hfin = HS + bb * 128 + (TT & 1) * 64;
        float s = fc_b[o];
#pragma unroll
        for (int k = 0; k < HH; ++k) s += hfin[k] * fc_w[o * HH + k];
        out[(b0 + bb) * 8 + o] = s;
    }
}

extern "C" void kernel_launch(void* const* d_in, const int* in_sizes, int n_in,
                              void* d_out, int out_size) {
    const float* x    = (const float*)d_in[0];
    const float* w_ih = (const float*)d_in[1];
    const float* w_hh = (const float*)d_in[2];
    const float* b_ih = (const float*)d_in[3];
    const float* b_hh = (const float*)d_in[4];
    const float* fc_w = (const float*)d_in[5];
    const float* fc_b = (const float*)d_in[6];
    float* out = (float*)d_out;

    const int B = in_sizes[0] / (TT * DD);   // 256

    static int attr_done = 0;
    if (!attr_done) {
        cudaFuncSetAttribute(lstm_q4,
                             cudaFuncAttributeMaxDynamicSharedMemorySize,
                             SMEM_BYTES);
        attr_done = 1;
    }
    lstm_q4<<<B / 2, 256, SMEM_BYTES>>>(x, w_ih, w_hh, b_ih, b_hh,
                                        fc_w, fc_b, out);
}